// round 16
// baseline (speedup 1.0000x reference)
#include <cuda_runtime.h>
#include <cuda_fp16.h>
#include <math.h>
#include <stdint.h>

#define BATCH 8
#define CIN   128
#define H     112
#define W     112
#define COUT  256
#define OFFC  18
#define HW    (H * W)
#define KC64  18        // k chunks of 64 (1152 total)

// ---------------------------------------------------------------------------
// Scratch (allocation-free rule: __device__ globals)
// ---------------------------------------------------------------------------
__device__ float g_offset[BATCH * OFFC * HW];
__device__ __align__(16) __half g_xt16[(size_t)BATCH * HW * CIN];
__device__ __align__(16) __half g_st16[(size_t)BATCH * HW * CIN];
__device__ __align__(16) __half g_wpre16[2 * KC64 * 128 * 64];
__device__ __align__(16) __half g_owpre16[KC64 * 32 * 64];

// k-permutation within a 32-block: memory position p -> source k-slot
__device__ __forceinline__ int kperm(int p) {
    int tc = p >> 3, j = p & 7, ks = j >> 2, jj = j & 3;
    return ks * 16 + 2 * tc + (jj & 1) + 8 * (jj >> 1);
}
__device__ __forceinline__ int kperm_inv(int r) {
    int ks = r >> 4, rr = r & 15, hi = rr >> 3, rem = rr & 7;
    int tc = rem >> 1, lo = rem & 1;
    return tc * 8 + lo + 2 * hi + 4 * ks;
}

// ---------------------------------------------------------------------------
// PTX helpers
// ---------------------------------------------------------------------------
__device__ __forceinline__ uint32_t smem_u32(const void* p) {
    uint32_t a;
    asm("{ .reg .u64 t; cvta.to.shared.u64 t, %1; cvt.u32.u64 %0, t; }" : "=r"(a) : "l"(p));
    return a;
}
__device__ __forceinline__ void cp16(uint32_t dst, const void* src) {
    asm volatile("cp.async.cg.shared.global [%0], [%1], 16;" :: "r"(dst), "l"(src) : "memory");
}
__device__ __forceinline__ void cp16z(uint32_t dst, const void* src, int srcsz) {
    asm volatile("cp.async.cg.shared.global [%0], [%1], 16, %2;"
                 :: "r"(dst), "l"(src), "r"(srcsz) : "memory");
}
#define CP_COMMIT() asm volatile("cp.async.commit_group;" ::: "memory")
#define CP_WAIT1()  asm volatile("cp.async.wait_group 1;" ::: "memory")
#define CP_WAIT0()  asm volatile("cp.async.wait_group 0;" ::: "memory")

__device__ __forceinline__ void mma_fp16(float* d,
        unsigned a0, unsigned a1, unsigned a2, unsigned a3,
        unsigned b0, unsigned b1) {
    asm volatile(
        "mma.sync.aligned.m16n8k16.row.col.f32.f16.f16.f32 "
        "{%0,%1,%2,%3}, {%4,%5,%6,%7}, {%8,%9}, {%0,%1,%2,%3};"
        : "+f"(d[0]), "+f"(d[1]), "+f"(d[2]), "+f"(d[3])
        : "r"(a0), "r"(a1), "r"(a2), "r"(a3), "r"(b0), "r"(b1));
}

struct __align__(8) h4pack { __half2 a, b; };

// ---------------------------------------------------------------------------
// Kernel 0: transpose x (B,C,H,W) fp32 -> g_xt16 (B,H,W,Cperm) fp16
// ---------------------------------------------------------------------------
__global__ void transpose_kernel(const float* __restrict__ x) {
    __shared__ float tile[CIN * 29];
    const int h = blockIdx.x;
    const int b = blockIdx.y;
    const int tid = threadIdx.x;
    for (int wc = 0; wc < 4; wc++) {
        for (int e = tid; e < CIN * 28; e += 256) {
            int c = e / 28, j = e % 28;
            tile[c * 29 + j] = x[((size_t)(b * CIN + c) * H + h) * W + wc * 28 + j];
        }
        __syncthreads();
        for (int e = tid; e < CIN * 28; e += 256) {
            int j = e >> 7, c = e & 127;
            int pc = (c & 96) | kperm_inv(c & 31);
            g_xt16[(((size_t)b * H + h) * W + wc * 28 + j) * CIN + pc] =
                __float2half_rn(tile[c * 29 + j]);
        }
        __syncthreads();
    }
}

// ---------------------------------------------------------------------------
// Kernel 1p: offset weight prep — fp16, permuted + swizzled, M padded to 32
// ---------------------------------------------------------------------------
__global__ void prep_ow_kernel(const float* __restrict__ ow) {
    const int c = blockIdx.x;           // 0..17
    const int pos = c >> 1;
    const int g   = c & 1;
    __half* dst = g_owpre16 + (size_t)c * 2048;
    for (int e = threadIdx.x; e < 2048; e += blockDim.x) {
        int m = e >> 6, p = e & 63;
        int blk = p >> 5;
        int ci = g * 64 + blk * 32 + kperm(p & 31);
        int phys = m * 64 + ((blk ^ (m & 1)) << 5) + (p & 31);
        float v = (m < OFFC) ? ow[(m * CIN + ci) * 9 + pos] : 0.f;
        dst[phys] = __float2half_rn(v);
    }
}

// ---------------------------------------------------------------------------
// Kernel 1: offset conv via fp16 MMA, 3-stage cp.async pipeline.
// CTA = (h-pair, b): M=32(18), N=224, K=1152. Writes g_offset directly.
// ---------------------------------------------------------------------------
#define OA_CH 4096u     // 32 rows * 128B
#define OB_CH 28672u    // 224 rows * 128B
#define O_STG (OA_CH + OB_CH)                 // 32768 per stage
#define OSMEM_TOT (3u * O_STG)                // 98304

__global__ void __launch_bounds__(256, 2) offset_mma_kernel(
        const float* __restrict__ ob) {
    extern __shared__ char smem[];
    const uint32_t sbase = smem_u32(smem);

    const int tid = threadIdx.x;
    const int wid = tid >> 5;
    const int lane = tid & 31;
    const int warp_m = wid & 1;
    const int warp_n = wid >> 1;
    const int tr = lane >> 2;
    const int tc = lane & 3;

    const int h0 = blockIdx.x * 2;
    const int b  = blockIdx.y;
    const __half* xtb = g_xt16 + (size_t)b * HW * CIN;

    float acc[7][4];
#pragma unroll
    for (int j = 0; j < 7; j++)
#pragma unroll
        for (int q = 0; q < 4; q++) acc[j][q] = 0.f;

    auto issue_copies = [&](int buf, int c) {
        uint32_t stg = sbase + buf * O_STG;
        cp16(stg + tid * 16, g_owpre16 + (size_t)c * 2048 + tid * 8);
        const int pos = c >> 1;
        const int g   = c & 1;
        const int ky = pos / 3, kx = pos % 3;
        uint32_t bdst = stg + OA_CH;
#pragma unroll
        for (int p = 0; p < 7; p++) {
            int e = tid + p * 256;
            int n = e >> 3, q = e & 7;
            int sh = (n >= 112) ? 1 : 0;
            int wv = n - sh * 112;
            int hrow = h0 + sh + ky - 1;
            int wi = wv + kx - 1;
            bool ok = (hrow >= 0) && (hrow < H) && (wi >= 0) && (wi < W);
            const __half* src = ok
                ? xtb + ((size_t)hrow * W + wi) * CIN + g * 64 + q * 8
                : xtb;
            uint32_t d = bdst + (uint32_t)(n * 128 + (((q >> 2) ^ (n & 1)) << 6)
                                           + (q & 3) * 16);
            cp16z(d, src, ok ? 16 : 0);
        }
    };

    issue_copies(0, 0); CP_COMMIT();
    issue_copies(1, 1); CP_COMMIT();

    const int trp = tr & 1;
    for (int c = 0; c < KC64; c++) {
        const int buf = c % 3;
        CP_WAIT1();
        __syncthreads();
        {
            const char* Ab = smem + buf * O_STG;
            const char* Bb = Ab + OA_CH;
#pragma unroll
            for (int ks = 0; ks < 2; ks++) {
                const int sel = (ks ^ trp) << 6;
                int r0 = warp_m * 16 + tr;
                uint4 aw0 = *reinterpret_cast<const uint4*>(Ab + r0 * 128 + sel + tc * 16);
                uint4 aw8 = *reinterpret_cast<const uint4*>(Ab + (r0 + 8) * 128 + sel + tc * 16);
#pragma unroll
                for (int j = 0; j < 7; j++) {
                    int n0 = warp_n * 56 + j * 8 + tr;
                    uint4 bw = *reinterpret_cast<const uint4*>(Bb + n0 * 128 + sel + tc * 16);
                    mma_fp16(acc[j], aw0.x, aw8.x, aw0.y, aw8.y, bw.x, bw.y);
                    mma_fp16(acc[j], aw0.z, aw8.z, aw0.w, aw8.w, bw.z, bw.w);
                }
            }
        }
        if (c + 2 < KC64) {
            issue_copies((c + 2) % 3, c + 2);
            CP_COMMIT();
        }
    }

    // epilogue: rows tr -> (c0,c1), tr+8 -> (c2,c3); add bias; write co < 18
    const int co = warp_m * 16 + tr;
#pragma unroll
    for (int j = 0; j < 7; j++) {
        int n0 = warp_n * 56 + j * 8 + tc * 2;
        int sh = (n0 >= 112) ? 1 : 0;
        int wv = n0 - sh * 112;
        if (co < OFFC) {
            float bb = ob[co];
            *reinterpret_cast<float2*>(
                g_offset + ((size_t)(b * OFFC + co) * H + h0 + sh) * W + wv) =
                make_float2(acc[j][0] + bb, acc[j][1] + bb);
        }
        if (co + 8 < OFFC) {
            float bb = ob[co + 8];
            *reinterpret_cast<float2*>(
                g_offset + ((size_t)(b * OFFC + co + 8) * H + h0 + sh) * W + wv) =
                make_float2(acc[j][2] + bb, acc[j][3] + bb);
        }
    }
}

// ---------------------------------------------------------------------------
// Kernel 2: sampling — uint16 idx + fp32 wt tables (24KB smem), fp16 gathers
// ---------------------------------------------------------------------------
__global__ void __launch_bounds__(128) sample_kernel() {
    __shared__ uint16_t sIdx[112 * 36];
    __shared__ float    sWt[112 * 36];
    const int h = blockIdx.x;
    const int b = blockIdx.y;
    const int tid = threadIdx.x;
    const int wid = tid >> 5;
    const int lane = tid & 31;

    if (tid < W) {
        const int w = tid;
        const float* offp = g_offset + (size_t)b * OFFC * HW + h * W + w;
#pragma unroll
        for (int p = 0; p < 9; p++) {
            int ky = p / 3, kx = p % 3;
            float offY = offp[(size_t)p * HW];
            float offX = offp[(size_t)(9 + p) * HW];
            float sy = (float)(h + ky - 1) + offY;
            float sx = (float)(w + kx - 1) + offX;
            float fy0 = floorf(sy), fx0 = floorf(sx);
            int y0 = (int)fy0, x0 = (int)fx0;
            float wy = sy - fy0, wx = sx - fx0;
#pragma unroll
            for (int q = 0; q < 4; q++) {
                int yi = y0 + (q >> 1), xi = x0 + (q & 1);
                float wgt = ((q >> 1) ? wy : 1.f - wy) * ((q & 1) ? wx : 1.f - wx);
                bool valid = (yi >= 0) & (yi < H) & (xi >= 0) & (xi < W);
                int yc = min(max(yi, 0), H - 1);
                int xc = min(max(xi, 0), W - 1);
                sIdx[w * 36 + p * 4 + q] = (uint16_t)(yc * W + xc);
                sWt[w * 36 + p * 4 + q] = valid ? wgt : 0.f;
            }
        }
    }
    __syncthreads();

    const __half* xtb = g_xt16 + (size_t)b * HW * CIN;
    __half* stb = g_st16 + (size_t)b * HW * CIN;
    for (int w = wid; w < W; w += 4) {
        float4 acc = make_float4(0.f, 0.f, 0.f, 0.f);
        const uint16_t* ti = &sIdx[w * 36];
        const float* tw = &sWt[w * 36];
#pragma unroll 9
        for (int q = 0; q < 36; q++) {
            int pix = ti[q];
            float wt = tw[q];
            h4pack v = *reinterpret_cast<const h4pack*>(xtb + (size_t)pix * CIN + lane * 4);
            float2 lo = __half22float2(v.a);
            float2 hi = __half22float2(v.b);
            acc.x += wt * lo.x; acc.y += wt * lo.y;
            acc.z += wt * hi.x; acc.w += wt * hi.y;
        }
        h4pack pk;
        pk.a = __floats2half2_rn(acc.x, acc.y);
        pk.b = __floats2half2_rn(acc.z, acc.w);
        *reinterpret_cast<h4pack*>(stb + (size_t)(h * W + w) * CIN + lane * 4) = pk;
    }
}

// ---------------------------------------------------------------------------
// Kernel 2.5: main conv weight prep — fp16, k-permuted + XOR swizzle baked
// ---------------------------------------------------------------------------
__global__ void prep_w_kernel(const float* __restrict__ cw) {
    const int c   = blockIdx.x;         // 0..17
    const int cog = blockIdx.y;         // 0..1
    const int pos = c >> 1;
    const int g   = c & 1;
    __half* dst = g_wpre16 + ((size_t)cog * KC64 + c) * 8192;
    for (int e = threadIdx.x; e < 8192; e += blockDim.x) {
        int m = e >> 6, p = e & 63;
        int blk = p >> 5;
        int ci = g * 64 + blk * 32 + kperm(p & 31);
        int co = cog * 128 + m;
        int phys = m * 64 + ((blk ^ (m & 1)) << 5) + (p & 31);
        dst[phys] = __float2half_rn(cw[(co * CIN + ci) * 9 + pos]);
    }
}

// ---------------------------------------------------------------------------
// Kernel 3: main conv, fp16 m16n8k16, K-chunk 64, 3-stage cp.async pipeline
// ---------------------------------------------------------------------------
#define SA_CH    16384u
#define SB_CH    14336u
#define C_STG    (SA_CH + SB_CH)              // 30720 per stage
#define SMEM_TOT (3u * C_STG)                 // 92160

__global__ void __launch_bounds__(256, 2) conv_mma_kernel(float* __restrict__ out) {
    extern __shared__ char smem[];
    const uint32_t sbase = smem_u32(smem);

    const int tid = threadIdx.x;
    const int wid = tid >> 5;
    const int lane = tid & 31;
    const int warp_m = wid & 3;
    const int warp_n = wid >> 2;
    const int tr = lane >> 2;
    const int tc = lane & 3;

    const int cog = blockIdx.x;
    const int h   = blockIdx.y;
    const int b   = blockIdx.z;
    const __half* stb = g_st16 + (size_t)b * HW * CIN;
    const __half* wbase = g_wpre16 + (size_t)cog * KC64 * 8192;

    float acc[2][7][4];
#pragma unroll
    for (int mt = 0; mt < 2; mt++)
#pragma unroll
        for (int j = 0; j < 7; j++)
#pragma unroll
            for (int q = 0; q < 4; q++) acc[mt][j][q] = 0.f;

    auto issue_copies = [&](int buf, int c) {
        uint32_t stg = sbase + buf * C_STG;
        const __half* wsrc = wbase + (size_t)c * 8192;
#pragma unroll
        for (int p = 0; p < 4; p++) {
            int e = tid + p * 256;
            cp16(stg + e * 16, wsrc + e * 8);
        }
        const int pos = c >> 1;
        const int g   = c & 1;
        const int ky = pos / 3, kx = pos % 3;
        const int hrow = h + ky - 1;
        const bool rowok = (hrow >= 0) && (hrow < H);
        uint32_t bdst = stg + SA_CH;
#pragma unroll
        for (int p = 0; p < 4; p++) {
            int e = tid + p * 256;
            if (e < 896) {
                int n = e >> 3, q = e & 7;
                int wi = n + kx - 1;
                bool ok = rowok && (wi >= 0) && (wi < W);
                const __half* src = ok
                    ? stb + ((size_t)hrow * W + wi) * CIN + g * 64 + q * 8
                    : stb;
                uint32_t d = bdst + (uint32_t)(n * 128 + (((q >> 2) ^ (n & 1)) << 6)
                                               + (q & 3) * 16);
                cp16z(d, src, ok ? 16 : 0);
            }
        }
    };

    issue_copies(0, 0); CP_COMMIT();
    issue_copies(1, 1); CP_COMMIT();

    const int trp = tr & 1;
    for (int c = 0; c < KC64; c++) {
        const int buf = c % 3;
        CP_WAIT1();
        __syncthreads();
        {
            const char* Ab = smem + buf * C_STG;
            const char* Bb = Ab + SA_CH;
#pragma unroll
            for (int ks = 0; ks < 2; ks++) {
                const int sel = (ks ^ trp) << 6;
                uint4 aw0[2], aw8[2];
#pragma unroll
                for (int mt = 0; mt < 2; mt++) {
                    int r0 = warp_m * 32 + mt * 16 + tr;
                    aw0[mt] = *reinterpret_cast<const uint4*>(Ab + r0 * 128 + sel + tc * 16);
                    aw8[mt] = *reinterpret_cast<const uint4*>(Ab + (r0 + 8) * 128 + sel + tc * 16);
                }
                uint4 bw[7];
#pragma unroll
                for (int j = 0; j < 7; j++) {
                    int n0 = warp_n * 56 + j * 8 + tr;
                    bw[j] = *reinterpret_cast<const uint4*>(Bb + n0 * 128 + sel + tc * 16);
                }
#pragma unroll
                for (int mt = 0; mt < 2; mt++)
#pragma unroll
                    for (int j = 0; j < 7; j++) {
                        mma_fp16(acc[mt][j], aw0[mt].x, aw8[mt].x, aw0[mt].y, aw8[mt].y,
                                 bw[j].x, bw[j].y);
                        mma_fp16(acc[mt][j], aw0[mt].z, aw8[mt].z, aw0[mt].w, aw8[mt].w,
                                 bw[j].z, bw[j].w);
                    }
            }
        }
        if (c + 2 < KC64) {
            issue_copies((c + 2) % 3, c + 2);
            CP_COMMIT();
        }
    }

#pragma unroll
    for (int mt = 0; mt < 2; mt++) {
        int r = warp_m * 32 + mt * 16 + tr;
        int co = cog * 128 + r;
#pragma unroll
        for (int j = 0; j < 7; j++) {
            int w0 = warp_n * 56 + j * 8 + tc * 2;
            float* op = out + (((size_t)b * COUT + co) * H + h) * W + w0;
            *reinterpret_cast<float2*>(op) = make_float2(acc[mt][j][0], acc[mt][j][1]);
            float* op2 = op + (size_t)8 * HW;
            *reinterpret_cast<float2*>(op2) = make_float2(acc[mt][j][2], acc[mt][j][3]);
        }
    }
}

// ---------------------------------------------------------------------------
extern "C" void kernel_launch(void* const* d_in, const int* in_sizes, int n_in,
                              void* d_out, int out_size) {
    const float* x  = (const float*)d_in[0];   // (8,128,112,112)
    const float* ow = (const float*)d_in[1];   // (18,128,3,3)
    const float* ob = (const float*)d_in[2];   // (18)
    const float* cw = (const float*)d_in[3];   // (256,128,3,3)
    float* out = (float*)d_out;                // (8,256,112,112)

    cudaFuncSetAttribute(conv_mma_kernel,
                         cudaFuncAttributeMaxDynamicSharedMemorySize, SMEM_TOT);
    cudaFuncSetAttribute(offset_mma_kernel,
                         cudaFuncAttributeMaxDynamicSharedMemorySize, OSMEM_TOT);

    dim3 grid_prep(KC64, 2);
    prep_w_kernel<<<grid_prep, 256>>>(cw);
    prep_ow_kernel<<<KC64, 256>>>(ow);
    dim3 grid_row(H, BATCH);
    transpose_kernel<<<grid_row, 256>>>(x);
    dim3 grid_offm(H / 2, BATCH);
    offset_mma_kernel<<<grid_offm, 256, OSMEM_TOT>>>(ob);
    sample_kernel<<<grid_row, 128>>>();
    dim3 grid_conv(2, H, BATCH);
    conv_mma_kernel<<<grid_conv, 256, SMEM_TOT>>>(out);
}

// round 17
// speedup vs baseline: 1.0485x; 1.0485x over previous
#include <cuda_runtime.h>
#include <cuda_fp16.h>
#include <math.h>
#include <stdint.h>

#define BATCH 8
#define CIN   128
#define H     112
#define W     112
#define COUT  256
#define OFFC  18
#define HW    (H * W)
#define KC64  18        // offset kernel: k chunks of 64

// ---------------------------------------------------------------------------
// Scratch (allocation-free rule: __device__ globals)
// ---------------------------------------------------------------------------
__device__ float g_offset[BATCH * OFFC * HW];
__device__ __align__(16) __half g_xt16[(size_t)BATCH * HW * CIN];
__device__ __align__(16) __half g_st16[(size_t)BATCH * HW * CIN];
// main conv weights fp16: [cog(2)][pos(9)][g(2)][m(128)][k(64)], k-permuted, NO xor
__device__ __align__(16) __half g_wpre16[2 * 9 * 2 * 128 * 64];
// offset conv weights fp16: [chunk(18)][m(32)][k(64)], permuted + XOR swizzle
__device__ __align__(16) __half g_owpre16[KC64 * 32 * 64];

// k-permutation within a 32-block: memory position p -> source k-slot
__device__ __forceinline__ int kperm(int p) {
    int tc = p >> 3, j = p & 7, ks = j >> 2, jj = j & 3;
    return ks * 16 + 2 * tc + (jj & 1) + 8 * (jj >> 1);
}
__device__ __forceinline__ int kperm_inv(int r) {
    int ks = r >> 4, rr = r & 15, hi = rr >> 3, rem = rr & 7;
    int tc = rem >> 1, lo = rem & 1;
    return tc * 8 + lo + 2 * hi + 4 * ks;
}

// ---------------------------------------------------------------------------
// PTX helpers
// ---------------------------------------------------------------------------
__device__ __forceinline__ uint32_t smem_u32(const void* p) {
    uint32_t a;
    asm("{ .reg .u64 t; cvta.to.shared.u64 t, %1; cvt.u32.u64 %0, t; }" : "=r"(a) : "l"(p));
    return a;
}
__device__ __forceinline__ void cp16(uint32_t dst, const void* src) {
    asm volatile("cp.async.cg.shared.global [%0], [%1], 16;" :: "r"(dst), "l"(src) : "memory");
}
__device__ __forceinline__ void cp16z(uint32_t dst, const void* src, int srcsz) {
    asm volatile("cp.async.cg.shared.global [%0], [%1], 16, %2;"
                 :: "r"(dst), "l"(src), "r"(srcsz) : "memory");
}
#define CP_COMMIT() asm volatile("cp.async.commit_group;" ::: "memory")
#define CP_WAIT1()  asm volatile("cp.async.wait_group 1;" ::: "memory")
#define CP_WAIT0()  asm volatile("cp.async.wait_group 0;" ::: "memory")

__device__ __forceinline__ void mma_fp16(float* d,
        unsigned a0, unsigned a1, unsigned a2, unsigned a3,
        unsigned b0, unsigned b1) {
    asm volatile(
        "mma.sync.aligned.m16n8k16.row.col.f32.f16.f16.f32 "
        "{%0,%1,%2,%3}, {%4,%5,%6,%7}, {%8,%9}, {%0,%1,%2,%3};"
        : "+f"(d[0]), "+f"(d[1]), "+f"(d[2]), "+f"(d[3])
        : "r"(a0), "r"(a1), "r"(a2), "r"(a3), "r"(b0), "r"(b1));
}

struct __align__(8) h4pack { __half2 a, b; };

// ---------------------------------------------------------------------------
// Kernel 0: transpose x (B,C,H,W) fp32 -> g_xt16 (B,H,W,Cperm) fp16
// ---------------------------------------------------------------------------
__global__ void transpose_kernel(const float* __restrict__ x) {
    __shared__ float tile[CIN * 29];
    const int h = blockIdx.x;
    const int b = blockIdx.y;
    const int tid = threadIdx.x;
    for (int wc = 0; wc < 4; wc++) {
        for (int e = tid; e < CIN * 28; e += 256) {
            int c = e / 28, j = e % 28;
            tile[c * 29 + j] = x[((size_t)(b * CIN + c) * H + h) * W + wc * 28 + j];
        }
        __syncthreads();
        for (int e = tid; e < CIN * 28; e += 256) {
            int j = e >> 7, c = e & 127;
            int pc = (c & 96) | kperm_inv(c & 31);
            g_xt16[(((size_t)b * H + h) * W + wc * 28 + j) * CIN + pc] =
                __float2half_rn(tile[c * 29 + j]);
        }
        __syncthreads();
    }
}

// ---------------------------------------------------------------------------
// Kernel 1p: offset weight prep — fp16, permuted + swizzled, M padded to 32
// ---------------------------------------------------------------------------
__global__ void prep_ow_kernel(const float* __restrict__ ow) {
    const int c = blockIdx.x;           // 0..17
    const int pos = c >> 1;
    const int g   = c & 1;
    __half* dst = g_owpre16 + (size_t)c * 2048;
    for (int e = threadIdx.x; e < 2048; e += blockDim.x) {
        int m = e >> 6, p = e & 63;
        int blk = p >> 5;
        int ci = g * 64 + blk * 32 + kperm(p & 31);
        int phys = m * 64 + ((blk ^ (m & 1)) << 5) + (p & 31);
        float v = (m < OFFC) ? ow[(m * CIN + ci) * 9 + pos] : 0.f;
        dst[phys] = __float2half_rn(v);
    }
}

// ---------------------------------------------------------------------------
// Kernel 1: offset conv via fp16 MMA, 3-stage cp.async pipeline (R16 config).
// ---------------------------------------------------------------------------
#define OA_CH 4096u
#define OB_CH 28672u
#define O_STG (OA_CH + OB_CH)
#define OSMEM_TOT (3u * O_STG)

__global__ void __launch_bounds__(256, 2) offset_mma_kernel(
        const float* __restrict__ ob) {
    extern __shared__ char smem[];
    const uint32_t sbase = smem_u32(smem);

    const int tid = threadIdx.x;
    const int wid = tid >> 5;
    const int lane = tid & 31;
    const int warp_m = wid & 1;
    const int warp_n = wid >> 1;
    const int tr = lane >> 2;
    const int tc = lane & 3;

    const int h0 = blockIdx.x * 2;
    const int b  = blockIdx.y;
    const __half* xtb = g_xt16 + (size_t)b * HW * CIN;

    float acc[7][4];
#pragma unroll
    for (int j = 0; j < 7; j++)
#pragma unroll
        for (int q = 0; q < 4; q++) acc[j][q] = 0.f;

    auto issue_copies = [&](int buf, int c) {
        uint32_t stg = sbase + buf * O_STG;
        cp16(stg + tid * 16, g_owpre16 + (size_t)c * 2048 + tid * 8);
        const int pos = c >> 1;
        const int g   = c & 1;
        const int ky = pos / 3, kx = pos % 3;
        uint32_t bdst = stg + OA_CH;
#pragma unroll
        for (int p = 0; p < 7; p++) {
            int e = tid + p * 256;
            int n = e >> 3, q = e & 7;
            int sh = (n >= 112) ? 1 : 0;
            int wv = n - sh * 112;
            int hrow = h0 + sh + ky - 1;
            int wi = wv + kx - 1;
            bool ok = (hrow >= 0) && (hrow < H) && (wi >= 0) && (wi < W);
            const __half* src = ok
                ? xtb + ((size_t)hrow * W + wi) * CIN + g * 64 + q * 8
                : xtb;
            uint32_t d = bdst + (uint32_t)(n * 128 + (((q >> 2) ^ (n & 1)) << 6)
                                           + (q & 3) * 16);
            cp16z(d, src, ok ? 16 : 0);
        }
    };

    issue_copies(0, 0); CP_COMMIT();
    issue_copies(1, 1); CP_COMMIT();

    const int trp = tr & 1;
    for (int c = 0; c < KC64; c++) {
        const int buf = c % 3;
        CP_WAIT1();
        __syncthreads();
        {
            const char* Ab = smem + buf * O_STG;
            const char* Bb = Ab + OA_CH;
#pragma unroll
            for (int ks = 0; ks < 2; ks++) {
                const int sel = (ks ^ trp) << 6;
                int r0 = warp_m * 16 + tr;
                uint4 aw0 = *reinterpret_cast<const uint4*>(Ab + r0 * 128 + sel + tc * 16);
                uint4 aw8 = *reinterpret_cast<const uint4*>(Ab + (r0 + 8) * 128 + sel + tc * 16);
#pragma unroll
                for (int j = 0; j < 7; j++) {
                    int n0 = warp_n * 56 + j * 8 + tr;
                    uint4 bw = *reinterpret_cast<const uint4*>(Bb + n0 * 128 + sel + tc * 16);
                    mma_fp16(acc[j], aw0.x, aw8.x, aw0.y, aw8.y, bw.x, bw.y);
                    mma_fp16(acc[j], aw0.z, aw8.z, aw0.w, aw8.w, bw.z, bw.w);
                }
            }
        }
        if (c + 2 < KC64) {
            issue_copies((c + 2) % 3, c + 2);
            CP_COMMIT();
        }
    }

    const int co = warp_m * 16 + tr;
#pragma unroll
    for (int j = 0; j < 7; j++) {
        int n0 = warp_n * 56 + j * 8 + tc * 2;
        int sh = (n0 >= 112) ? 1 : 0;
        int wv = n0 - sh * 112;
        if (co < OFFC) {
            float bb = ob[co];
            *reinterpret_cast<float2*>(
                g_offset + ((size_t)(b * OFFC + co) * H + h0 + sh) * W + wv) =
                make_float2(acc[j][0] + bb, acc[j][1] + bb);
        }
        if (co + 8 < OFFC) {
            float bb = ob[co + 8];
            *reinterpret_cast<float2*>(
                g_offset + ((size_t)(b * OFFC + co + 8) * H + h0 + sh) * W + wv) =
                make_float2(acc[j][2] + bb, acc[j][3] + bb);
        }
    }
}

// ---------------------------------------------------------------------------
// Kernel 2: sampling — uint16 idx + fp32 wt tables, fp16 gathers
// ---------------------------------------------------------------------------
__global__ void __launch_bounds__(128) sample_kernel() {
    __shared__ uint16_t sIdx[112 * 36];
    __shared__ float    sWt[112 * 36];
    const int h = blockIdx.x;
    const int b = blockIdx.y;
    const int tid = threadIdx.x;
    const int wid = tid >> 5;
    const int lane = tid & 31;

    if (tid < W) {
        const int w = tid;
        const float* offp = g_offset + (size_t)b * OFFC * HW + h * W + w;
#pragma unroll
        for (int p = 0; p < 9; p++) {
            int ky = p / 3, kx = p % 3;
            float offY = offp[(size_t)p * HW];
            float offX = offp[(size_t)(9 + p) * HW];
            float sy = (float)(h + ky - 1) + offY;
            float sx = (float)(w + kx - 1) + offX;
            float fy0 = floorf(sy), fx0 = floorf(sx);
            int y0 = (int)fy0, x0 = (int)fx0;
            float wy = sy - fy0, wx = sx - fx0;
#pragma unroll
            for (int q = 0; q < 4; q++) {
                int yi = y0 + (q >> 1), xi = x0 + (q & 1);
                float wgt = ((q >> 1) ? wy : 1.f - wy) * ((q & 1) ? wx : 1.f - wx);
                bool valid = (yi >= 0) & (yi < H) & (xi >= 0) & (xi < W);
                int yc = min(max(yi, 0), H - 1);
                int xc = min(max(xi, 0), W - 1);
                sIdx[w * 36 + p * 4 + q] = (uint16_t)(yc * W + xc);
                sWt[w * 36 + p * 4 + q] = valid ? wgt : 0.f;
            }
        }
    }
    __syncthreads();

    const __half* xtb = g_xt16 + (size_t)b * HW * CIN;
    __half* stb = g_st16 + (size_t)b * HW * CIN;
    for (int w = wid; w < W; w += 4) {
        float4 acc = make_float4(0.f, 0.f, 0.f, 0.f);
        const uint16_t* ti = &sIdx[w * 36];
        const float* tw = &sWt[w * 36];
#pragma unroll 9
        for (int q = 0; q < 36; q++) {
            int pix = ti[q];
            float wt = tw[q];
            h4pack v = *reinterpret_cast<const h4pack*>(xtb + (size_t)pix * CIN + lane * 4);
            float2 lo = __half22float2(v.a);
            float2 hi = __half22float2(v.b);
            acc.x += wt * lo.x; acc.y += wt * lo.y;
            acc.z += wt * hi.x; acc.w += wt * hi.y;
        }
        h4pack pk;
        pk.a = __floats2half2_rn(acc.x, acc.y);
        pk.b = __floats2half2_rn(acc.z, acc.w);
        *reinterpret_cast<h4pack*>(stb + (size_t)(h * W + w) * CIN + lane * 4) = pk;
    }
}

// ---------------------------------------------------------------------------
// Kernel 2.5: main conv weight prep — [cog][pos][g][m128][k64], k-permuted,
// NO xor swizzle (A read by direct LDG now).
// ---------------------------------------------------------------------------
__global__ void prep_w_kernel(const float* __restrict__ cw) {
    const int c   = blockIdx.x;         // 0..17: pos = c>>1, g = c&1
    const int cog = blockIdx.y;
    const int pos = c >> 1;
    const int g   = c & 1;
    __half* dst = g_wpre16 + (((size_t)cog * 9 + pos) * 2 + g) * 8192;
    for (int e = threadIdx.x; e < 8192; e += blockDim.x) {
        int m = e >> 6, p = e & 63;
        int blk = p >> 5;
        int ci = g * 64 + blk * 32 + kperm(p & 31);
        int co = cog * 128 + m;
        dst[m * 64 + p] = __float2half_rn(cw[(co * CIN + ci) * 9 + pos]);
    }
}

// ---------------------------------------------------------------------------
// Kernel 3: main conv — X-tile formulation.
// CTA = (cog, h, b). Per channel-half g: load raw 3x114x64ch fp16 halo tile
// into smem ONCE (2736 cp16, XOR half-swizzled by pixel parity), then loop
// the 9 positions reading B fragments straight from the tile and A fragments
// straight from global (L2-resident weights). Zero syncs in the pos loop.
// ---------------------------------------------------------------------------
#define XP    114
#define X_CH  (3u * XP * 128u)    // 43776 per half
#define SMEM_TOT (2u * X_CH)      // 87552

__global__ void __launch_bounds__(256, 2) conv_mma_kernel(float* __restrict__ out) {
    extern __shared__ char smem[];
    const uint32_t sbase = smem_u32(smem);

    const int tid = threadIdx.x;
    const int wid = tid >> 5;
    const int lane = tid & 31;
    const int warp_m = wid & 3;
    const int warp_n = wid >> 2;
    const int tr = lane >> 2;
    const int tc = lane & 3;

    const int cog = blockIdx.x;
    const int h   = blockIdx.y;
    const int b   = blockIdx.z;
    const __half* stb = g_st16 + (size_t)b * HW * CIN;

    float acc[2][7][4];
#pragma unroll
    for (int mt = 0; mt < 2; mt++)
#pragma unroll
        for (int j = 0; j < 7; j++)
#pragma unroll
            for (int q = 0; q < 4; q++) acc[mt][j][q] = 0.f;

    // X-tile copy for half g into buffer buf: rows h-1..h+1, pixels wi=-1..112
    auto copyX = [&](int buf, int g) {
        uint32_t dstb = sbase + buf * X_CH;
#pragma unroll
        for (int pp = 0; pp < 15; pp++) {
            int e = tid + pp * 256;
            if (e < 3 * XP * 8) {
                int r = e / (XP * 8);
                int rem = e % (XP * 8);
                int p = rem >> 3, q = rem & 7;
                int hrow = h + r - 1;
                int wi = p - 1;
                bool ok = (hrow >= 0) && (hrow < H) && (wi >= 0) && (wi < W);
                const __half* src = ok
                    ? stb + ((size_t)hrow * W + wi) * CIN + g * 64 + q * 8
                    : stb;
                uint32_t d = dstb + (uint32_t)(r * (XP * 128) + p * 128
                              + (((q >> 2) ^ (p & 1)) << 6) + (q & 3) * 16);
                cp16z(d, src, ok ? 16 : 0);
            }
        }
    };

    copyX(0, 0); CP_COMMIT();
    copyX(1, 1); CP_COMMIT();
    CP_WAIT1();
    __syncthreads();

    for (int g = 0; g < 2; g++) {
        if (g == 1) { CP_WAIT0(); __syncthreads(); }
        const char* Xb = smem + g * X_CH;
#pragma unroll 3
        for (int pos = 0; pos < 9; pos++) {
            const int ky = pos / 3, kx = pos % 3;
            // A fragments straight from global (uint4 index = r*8 + ks*4 + tc)
            const uint4* Ag = reinterpret_cast<const uint4*>(
                g_wpre16 + (((size_t)cog * 9 + pos) * 2 + g) * 8192);
            uint4 aw0[2][2], aw8[2][2];   // [ks][mt]
#pragma unroll
            for (int ks = 0; ks < 2; ks++)
#pragma unroll
                for (int mt = 0; mt < 2; mt++) {
                    int r0 = warp_m * 32 + mt * 16 + tr;
                    aw0[ks][mt] = Ag[r0 * 8 + ks * 4 + tc];
                    aw8[ks][mt] = Ag[(r0 + 8) * 8 + ks * 4 + tc];
                }
            const int par = (tr + kx) & 1;
            const char* Xrow = Xb + ky * (XP * 128)
                             + (warp_n * 56 + kx + tr) * 128 + tc * 16;
#pragma unroll
            for (int ks = 0; ks < 2; ks++) {
                const int sel = (ks ^ par) << 6;
#pragma unroll
                for (int j = 0; j < 7; j++) {
                    uint4 bw = *reinterpret_cast<const uint4*>(Xrow + j * 1024 + sel);
#pragma unroll
                    for (int mt = 0; mt < 2; mt++) {
                        mma_fp16(acc[mt][j],
                                 aw0[ks][mt].x, aw8[ks][mt].x,
                                 aw0[ks][mt].y, aw8[ks][mt].y, bw.x, bw.y);
                        mma_fp16(acc[mt][j],
                                 aw0[ks][mt].z, aw8[ks][mt].z,
                                 aw0[ks][mt].w, aw8[ks][mt].w, bw.z, bw.w);
                    }
                }
            }
        }
    }

    // epilogue
#pragma unroll
    for (int mt = 0; mt < 2; mt++) {
        int r = warp_m * 32 + mt * 16 + tr;
        int co = cog * 128 + r;
#pragma unroll
        for (int j = 0; j < 7; j++) {
            int w0 = warp_n * 56 + j * 8 + tc * 2;
            float* op = out + (((size_t)b * COUT + co) * H + h) * W + w0;
            *reinterpret_cast<float2*>(op) = make_float2(acc[mt][j][0], acc[mt][j][1]);
            float* op2 = op + (size_t)8 * HW;   // co + 8
            *reinterpret_cast<float2*>(op2) = make_float2(acc[mt][j][2], acc[mt][j][3]);
        }
    }
}

// ---------------------------------------------------------------------------
extern "C" void kernel_launch(void* const* d_in, const int* in_sizes, int n_in,
                              void* d_out, int out_size) {
    const float* x  = (const float*)d_in[0];   // (8,128,112,112)
    const float* ow = (const float*)d_in[1];   // (18,128,3,3)
    const float* ob = (const float*)d_in[2];   // (18)
    const float* cw = (const float*)d_in[3];   // (256,128,3,3)
    float* out = (float*)d_out;                // (8,256,112,112)

    cudaFuncSetAttribute(conv_mma_kernel,
                         cudaFuncAttributeMaxDynamicSharedMemorySize, SMEM_TOT);
    cudaFuncSetAttribute(offset_mma_kernel,
                         cudaFuncAttributeMaxDynamicSharedMemorySize, OSMEM_TOT);

    dim3 grid_prep(18, 2);
    prep_w_kernel<<<grid_prep, 256>>>(cw);
    prep_ow_kernel<<<KC64, 256>>>(ow);
    dim3 grid_row(H, BATCH);
    transpose_kernel<<<grid_row, 256>>>(x);
    dim3 grid_offm(H / 2, BATCH);
    offset_mma_kernel<<<grid_offm, 256, OSMEM_TOT>>>(ob);
    sample_kernel<<<grid_row, 128>>>();
    dim3 grid_conv(2, H, BATCH);
    conv_mma_kernel<<<grid_conv, 256, SMEM_TOT>>>(out);
}